// round 10
// baseline (speedup 1.0000x reference)
#include <cuda_runtime.h>
#include <cuda_bf16.h>
#include <cuda_fp16.h>
#include <cstdint>

// ---------------------------------------------------------------------------
// out[n] = ||delta_n||^2 (exact fp32) + (1/512)*delta @ (512*(S_inv-I)) @ delta^T
// Symmetric S_inv => lower-triangle 128x128 blocks only (off-diag weight 2).
// fp8 e4m3 mma.sync m16n8k32.  Persistent warp-specialized pipeline:
// warps 0-7 produce (stream x/x_fit -> fp8 A, rowsq), warps 8-15 consume (GEMM).
// ---------------------------------------------------------------------------

#define NROWS  65536
#define NBLK   512
#define GRID   148

// fp8 512*(S_inv - I), 16 tiles of 16KB: tile t=(n>>7)*4+(k>>7),
// in-tile: nn*128 + (kk ^ ((nn&7)<<4))  -- SMEM image == GMEM image.
__device__ __align__(16) unsigned char g_B[512 * 512];

__constant__ int c_nc[10] = {0,1,1,2,2,2,3,3,3,3};
__constant__ int c_kc[10] = {0,0,1,0,1,2,0,1,2,3};

#define SM_MBAR  0                      // full0@0 full1@8 empty0@16 empty1@24
#define SM_ROWSQ 64                     // 2 x 128 floats
#define SM_PART  1152                   // 512 floats
#define SM_A     4096                   // 2 x 65536 (fp8 delta, swizzled)
#define SM_B     (SM_A + 2 * 65536)     // 2 x 16384 double buffer
#define SM_TOTAL (SM_B + 2 * 16384)     // 167936 bytes

__device__ __forceinline__ uint32_t smem_u32(const void* p) {
    uint32_t a;
    asm("{ .reg .u64 t; cvta.to.shared.u64 t, %1; cvt.u32.u64 %0, t; }"
        : "=r"(a) : "l"(p));
    return a;
}

__device__ __forceinline__ void ldsm4(uint32_t* r, uint32_t addr) {
    asm volatile("ldmatrix.sync.aligned.m8n8.x4.shared.b16 {%0,%1,%2,%3}, [%4];"
                 : "=r"(r[0]), "=r"(r[1]), "=r"(r[2]), "=r"(r[3]) : "r"(addr));
}

__device__ __forceinline__ void mma16832(float* d, const uint32_t* a,
                                         const uint32_t* b) {
    asm volatile(
        "mma.sync.aligned.m16n8k32.row.col.f32.e4m3.e4m3.f32 "
        "{%0,%1,%2,%3}, {%4,%5,%6,%7}, {%8,%9}, {%0,%1,%2,%3};"
        : "+f"(d[0]), "+f"(d[1]), "+f"(d[2]), "+f"(d[3])
        : "r"(a[0]), "r"(a[1]), "r"(a[2]), "r"(a[3]),
          "r"(b[0]), "r"(b[1]));
}

__device__ __forceinline__ void cp16(uint32_t dst, const void* src) {
    asm volatile("cp.async.cg.shared.global [%0], [%1], 16;"
                 :: "r"(dst), "l"(src));
}

__device__ __forceinline__ uint16_t f2e4m3x2(float hi, float lo) {
    uint16_t r;
    asm("cvt.rn.satfinite.e4m3x2.f32 %0, %1, %2;" : "=h"(r) : "f"(hi), "f"(lo));
    return r;
}

__device__ __forceinline__ float2 e4m3x2_2f(uint16_t v) {
    uint32_t h;
    asm("cvt.rn.f16x2.e4m3x2 %0, %1;" : "=r"(h) : "h"(v));
    return __half22float2(*reinterpret_cast<__half2*>(&h));
}

__device__ __forceinline__ void mbar_wait(uint32_t mbar, uint32_t parity) {
    asm volatile(
        "{\n\t.reg .pred P;\n\t"
        "WAITLOOP%=:\n\t"
        "mbarrier.try_wait.parity.acquire.cta.shared::cta.b64 P, [%0], %1, 0x989680;\n\t"
        "@!P bra WAITLOOP%=;\n\t}"
        :: "r"(mbar), "r"(parity) : "memory");
}

__device__ __forceinline__ void mbar_arrive(uint32_t mbar) {
    asm volatile("mbarrier.arrive.shared.b64 _, [%0];" :: "r"(mbar) : "memory");
}

#define BAR3() asm volatile("bar.sync 3, 256;" ::: "memory")

// ---------------------------------------------------------------------------
__global__ void __launch_bounds__(256, 4)
prep_kernel(const float* __restrict__ S) {
    int p = blockIdx.x * 256 + threadIdx.x;
    int n = p >> 8;
    int k = (p & 255) << 1;
    float v0 = (S[n * 512 + k]     - (n == k     ? 1.0f : 0.0f)) * 512.0f;
    float v1 = (S[n * 512 + k + 1] - (n == k + 1 ? 1.0f : 0.0f)) * 512.0f;
    int t = (n >> 7) * 4 + (k >> 7);
    uint32_t nn = (uint32_t)(n & 127), kk = (uint32_t)(k & 127);
    uint32_t off = (uint32_t)(t * 16384) + nn * 128 + (kk ^ ((nn & 7) << 4));
    *(uint16_t*)(g_B + off) = f2e4m3x2(v1, v0);
}

// ---------------------------------------------------------------------------
extern __shared__ unsigned char smem[];

__global__ void __launch_bounds__(512, 1)
mahal_kernel(const float4* __restrict__ x4, const float4* __restrict__ f4,
             float* __restrict__ out) {
    const int tid  = threadIdx.x;
    const int wid  = tid >> 5;
    const int lane = tid & 31;
    const uint32_t sbase = smem_u32(smem);

    if (tid == 0) {
        #pragma unroll
        for (int b = 0; b < 4; b++)
            asm volatile("mbarrier.init.shared.b64 [%0], 256;"
                         :: "r"(sbase + SM_MBAR + b * 8) : "memory");
    }
    __syncthreads();

    if (wid < 8) {
        // =================== PRODUCER: warps 0-7 ===================
        int ph0 = 1, ph1 = 1;
        int j = 0;
        const int r0 = wid * 16;
        for (int blk = blockIdx.x; blk < NBLK; blk += GRID, j++) {
            const int b = j & 1;
            mbar_wait(sbase + SM_MBAR + 16 + b * 8, b ? ph1 : ph0);
            if (b) ph1 ^= 1; else ph0 ^= 1;

            const uint32_t abase = (uint32_t)(SM_A + b * 65536);
            float* rowsqb = (float*)(smem + SM_ROWSQ + b * 512);
            const int m0 = blk * 128;

            for (int rr = 0; rr < 16; rr++) {
                int r = r0 + rr;
                long gbase = (long)(m0 + r) * 128;
                float sq = 0.0f;
                uint32_t rswz = (uint32_t)(r & 7) << 4;
                #pragma unroll
                for (int q = 0; q < 4; q++) {
                    int c4 = lane + q * 32;
                    float4 xv = x4[gbase + c4];
                    float4 fv = f4[gbase + c4];
                    float d0 = xv.x - fv.x, d1 = xv.y - fv.y;
                    float d2 = xv.z - fv.z, d3 = xv.w - fv.w;
                    sq += d0 * d0 + d1 * d1 + d2 * d2 + d3 * d3;
                    uint32_t v = (uint32_t)f2e4m3x2(d1, d0)
                               | ((uint32_t)f2e4m3x2(d3, d2) << 16);
                    uint32_t off = abase + (uint32_t)(r * 512)
                                 + (((uint32_t)(c4 * 4)) ^ rswz);
                    *(uint32_t*)(smem + off) = v;
                }
                #pragma unroll
                for (int o = 16; o; o >>= 1)
                    sq += __shfl_xor_sync(0xffffffffu, sq, o);
                if (lane == 0) rowsqb[r] = sq;
            }
            mbar_arrive(sbase + SM_MBAR + b * 8);   // full[b]
        }
    } else {
        // =================== CONSUMER: warps 8-15 ===================
        const int ctid = tid - 256;
        const int w  = wid - 8;
        const int mb = w >> 2;
        const int nb = w & 3;
        const uint32_t aswz  = (uint32_t)(lane & 7) << 4;
        const uint32_t akoff = (uint32_t)(lane >> 4) << 4;
        const int bn1 = (lane & 7) + ((lane >> 4) << 3);
        const uint32_t bkoff = (uint32_t)((lane >> 3) & 1) << 4;

        uint32_t a_row[4];
        #pragma unroll
        for (int sm = 0; sm < 4; sm++)
            a_row[sm] = (uint32_t)((mb * 64 + sm * 16 + (lane & 15)) * 512);
        uint32_t b_off[2];
        #pragma unroll
        for (int sn = 0; sn < 2; sn++)
            b_off[sn] = (uint32_t)((nb * 32 + sn * 16 + bn1) * 128);

        const int rq = lane >> 2;
        uint32_t d_base[4];
        const uint32_t d_swz = (uint32_t)((mb * 64 + rq) & 7) << 4;
        #pragma unroll
        for (int sm = 0; sm < 4; sm++)
            d_base[sm] = (uint32_t)((mb * 64 + sm * 16 + rq) * 512);

        float* part = (float*)(smem + SM_PART);

        const int nmy  = (NBLK - 1 - (int)blockIdx.x) / GRID + 1;
        const int ftot = nmy * 10;

        // prefetch flat tiles 0,1 (tile ids 0 and 4)
        #pragma unroll
        for (int t = 0; t < 2; t++) {
            uint32_t dst = sbase + SM_B + t * 16384;
            const unsigned char* src = g_B + (t ? 4 : 0) * 16384;
            #pragma unroll
            for (int i = 0; i < 4; i++) {
                int e = ctid + i * 256;
                cp16(dst + e * 16, src + e * 16);
            }
            asm volatile("cp.async.commit_group;");
        }

        int fl0 = 0, fl1 = 0;
        int f = 0, j = 0;
        for (int blk = blockIdx.x; blk < NBLK; blk += GRID, j++) {
            const int b = j & 1;
            mbar_wait(sbase + SM_MBAR + b * 8, b ? fl1 : fl0);   // full[b]
            if (b) fl1 ^= 1; else fl0 ^= 1;

            const uint32_t abase = sbase + SM_A + (uint32_t)(b * 65536);
            const int m0 = blk * 128;

            float zl[4] = {0, 0, 0, 0}, zh[4] = {0, 0, 0, 0};

            #pragma unroll 1
            for (int ti = 0; ti < 10; ti++, f++) {
                const int nc = c_nc[ti], kc = c_kc[ti];
                asm volatile("cp.async.wait_group 1;" ::: "memory");
                BAR3();

                const uint32_t btile = sbase + SM_B + (f & 1) * 16384;

                float acc[4][4][4];
                #pragma unroll
                for (int sm = 0; sm < 4; sm++)
                    #pragma unroll
                    for (int jj = 0; jj < 4; jj++)
                        #pragma unroll
                        for (int q = 0; q < 4; q++)
                            acc[sm][jj][q] = 0.0f;

                #pragma unroll
                for (int s = 0; s < 4; s++) {
                    uint32_t af[4][4], bf[2][4];
                    uint32_t akb = (uint32_t)(kc * 128 + s * 32);
                    #pragma unroll
                    for (int sm = 0; sm < 4; sm++)
                        ldsm4(af[sm], abase + a_row[sm] + ((akb + akoff) ^ aswz));
                    #pragma unroll
                    for (int sn = 0; sn < 2; sn++)
                        ldsm4(bf[sn], btile + b_off[sn]
                              + (((uint32_t)(s * 32) + bkoff) ^ aswz));
                    #pragma unroll
                    for (int sm = 0; sm < 4; sm++)
                        #pragma unroll
                        for (int jj = 0; jj < 4; jj++)
                            mma16832(acc[sm][jj], af[sm], bf[jj >> 1] + (jj & 1) * 2);
                }

                const float wgt = (nc == kc) ? 1.0f : 2.0f;
                #pragma unroll
                for (int sm = 0; sm < 4; sm++) {
                    #pragma unroll
                    for (int jj = 0; jj < 4; jj++) {
                        uint32_t kbyte = (uint32_t)(nc * 128 + nb * 32 + jj * 8
                                                    + (lane & 3) * 2);
                        uint32_t off = kbyte ^ d_swz;
                        uint16_t vlo = *(const uint16_t*)((unsigned char*)smem
                                         + (abase - sbase) + d_base[sm] + off);
                        uint16_t vhi = *(const uint16_t*)((unsigned char*)smem
                                         + (abase - sbase) + d_base[sm] + 8 * 512 + off);
                        float2 flo = e4m3x2_2f(vlo);
                        float2 fhi = e4m3x2_2f(vhi);
                        zl[sm] += wgt * (flo.x * acc[sm][jj][0]
                                       + flo.y * acc[sm][jj][1]);
                        zh[sm] += wgt * (fhi.x * acc[sm][jj][2]
                                       + fhi.y * acc[sm][jj][3]);
                    }
                }

                BAR3();

                if (f + 2 < ftot) {
                    int fid = f + 2;
                    int ii = fid % 10;
                    int tile = c_nc[ii] * 4 + c_kc[ii];
                    uint32_t dst = sbase + SM_B + (f & 1) * 16384;
                    const unsigned char* src = g_B + tile * 16384;
                    #pragma unroll
                    for (int i = 0; i < 4; i++) {
                        int e = ctid + i * 256;
                        cp16(dst + e * 16, src + e * 16);
                    }
                }
                asm volatile("cp.async.commit_group;");
            }

            // reduce + stage partials
            #pragma unroll
            for (int sm = 0; sm < 4; sm++) {
                zl[sm] += __shfl_xor_sync(0xffffffffu, zl[sm], 1);
                zl[sm] += __shfl_xor_sync(0xffffffffu, zl[sm], 2);
                zh[sm] += __shfl_xor_sync(0xffffffffu, zh[sm], 1);
                zh[sm] += __shfl_xor_sync(0xffffffffu, zh[sm], 2);
            }
            if ((lane & 3) == 0) {
                #pragma unroll
                for (int sm = 0; sm < 4; sm++) {
                    int row = mb * 64 + sm * 16 + (lane >> 2);
                    part[nb * 128 + row]     = zl[sm];
                    part[nb * 128 + row + 8] = zh[sm];
                }
            }
            BAR3();

            if (ctid < 128) {
                const float* rowsqb = (const float*)(smem + SM_ROWSQ + b * 512);
                out[m0 + ctid] = rowsqb[ctid]
                               + (part[ctid] + part[128 + ctid]
                                  + part[256 + ctid] + part[384 + ctid])
                                 * (1.0f / 512.0f);
            }
            mbar_arrive(sbase + SM_MBAR + 16 + b * 8);   // empty[b]
            BAR3();
        }
    }
}

// ---------------------------------------------------------------------------
extern "C" void kernel_launch(void* const* d_in, const int* in_sizes, int n_in,
                              void* d_out, int out_size) {
    const float* x  = (const float*)d_in[0];
    const float* xf = (const float*)d_in[1];
    const float* S  = (const float*)d_in[2];
    float* out = (float*)d_out;

    cudaFuncSetAttribute(mahal_kernel,
                         cudaFuncAttributeMaxDynamicSharedMemorySize, SM_TOTAL);

    prep_kernel<<<512, 256>>>(S);
    mahal_kernel<<<GRID, 512, SM_TOTAL>>>(
        (const float4*)x, (const float4*)xf, out);
}

// round 11
// speedup vs baseline: 1.0607x; 1.0607x over previous
#include <cuda_runtime.h>
#include <cuda_bf16.h>
#include <cuda_fp16.h>
#include <cstdint>

// ---------------------------------------------------------------------------
// out[n] = ||delta_n||^2 (exact fp32) + (1/512)*delta @ W @ delta^T
// W = 512*(S_inv - I) with off-diagonal-block weight 2 PRE-FOLDED (symmetry:
// only lower-triangle 128x128 blocks computed).  fp8 e4m3 mma.sync m16n8k32.
// 2 CTAs/SM; acc accumulates across kc inside each nc-group (4 dots total).
// ---------------------------------------------------------------------------

#define NROWS 65536
#define MTILE 128

// fp8 weighted 512*(S_inv - I), 16 tiles of 16KB: tile t=(n>>7)*4+(k>>7),
// in-tile: nn*128 + (kk ^ ((nn&7)<<4))  -- SMEM image == GMEM image.
__device__ __align__(16) unsigned char g_B[512 * 512];

#define SM_ROWSQ 0                     // 128 floats
#define SM_PART  512                   // 512 floats
#define SM_A     4096                  // 128 rows x 512B fp8 delta (swizzled)
#define SM_B     (SM_A + 65536)        // 2 x 16KB double buffer
#define SM_TOTAL (SM_B + 2 * 16384)    // 102400 bytes

__device__ __forceinline__ uint32_t smem_u32(const void* p) {
    uint32_t a;
    asm("{ .reg .u64 t; cvta.to.shared.u64 t, %1; cvt.u32.u64 %0, t; }"
        : "=r"(a) : "l"(p));
    return a;
}

__device__ __forceinline__ void ldsm4(uint32_t* r, uint32_t addr) {
    asm volatile("ldmatrix.sync.aligned.m8n8.x4.shared.b16 {%0,%1,%2,%3}, [%4];"
                 : "=r"(r[0]), "=r"(r[1]), "=r"(r[2]), "=r"(r[3]) : "r"(addr));
}

__device__ __forceinline__ void mma16832(float* d, const uint32_t* a,
                                         const uint32_t* b) {
    asm volatile(
        "mma.sync.aligned.m16n8k32.row.col.f32.e4m3.e4m3.f32 "
        "{%0,%1,%2,%3}, {%4,%5,%6,%7}, {%8,%9}, {%0,%1,%2,%3};"
        : "+f"(d[0]), "+f"(d[1]), "+f"(d[2]), "+f"(d[3])
        : "r"(a[0]), "r"(a[1]), "r"(a[2]), "r"(a[3]),
          "r"(b[0]), "r"(b[1]));
}

__device__ __forceinline__ void cp16(uint32_t dst, const void* src) {
    asm volatile("cp.async.cg.shared.global [%0], [%1], 16;"
                 :: "r"(dst), "l"(src));
}

__device__ __forceinline__ uint16_t f2e4m3x2(float hi, float lo) {
    uint16_t r;
    asm("cvt.rn.satfinite.e4m3x2.f32 %0, %1, %2;" : "=h"(r) : "f"(hi), "f"(lo));
    return r;
}

__device__ __forceinline__ float2 e4m3x2_2f(uint16_t v) {
    uint32_t h;
    asm("cvt.rn.f16x2.e4m3x2 %0, %1;" : "=r"(h) : "h"(v));
    return __half22float2(*reinterpret_cast<__half2*>(&h));
}

// ---------------------------------------------------------------------------
// Prep: weight 2 for off-diagonal blocks folded into the fp8 matrix.
// ---------------------------------------------------------------------------
__global__ void __launch_bounds__(256, 4)
prep_kernel(const float* __restrict__ S) {
    int p = blockIdx.x * 256 + threadIdx.x;   // 131072 threads, 2 elems each
    int n = p >> 8;
    int k = (p & 255) << 1;
    float wgt = ((n >> 7) == (k >> 7)) ? 512.0f : 1024.0f;
    float v0 = (S[n * 512 + k]     - (n == k     ? 1.0f : 0.0f)) * wgt;
    float v1 = (S[n * 512 + k + 1] - (n == k + 1 ? 1.0f : 0.0f)) * wgt;
    int t = (n >> 7) * 4 + (k >> 7);
    uint32_t nn = (uint32_t)(n & 127), kk = (uint32_t)(k & 127);
    uint32_t off = (uint32_t)(t * 16384) + nn * 128 + (kk ^ ((nn & 7) << 4));
    *(uint16_t*)(g_B + off) = f2e4m3x2(v1, v0);
}

// ---------------------------------------------------------------------------
extern __shared__ unsigned char smem[];

__global__ void __launch_bounds__(256, 2)
mahal_kernel(const float4* __restrict__ x4, const float4* __restrict__ f4,
             float* __restrict__ out) {
    const int tid  = threadIdx.x;
    const int wid  = tid >> 5;
    const int lane = tid & 31;
    const int m0   = blockIdx.x * MTILE;
    const uint32_t sbase = smem_u32(smem);
    float* rowsq = (float*)(smem + SM_ROWSQ);
    float* part  = (float*)(smem + SM_PART);

    // --- prefetch first two triangle tiles: (0,0)->t0, (1,0)->t4 ---
    {
        uint32_t dst = sbase + SM_B;
        #pragma unroll
        for (int i = 0; i < 4; i++) {
            int e = tid + i * 256;
            cp16(dst + e * 16, g_B + e * 16);
        }
        asm volatile("cp.async.commit_group;");
        dst += 16384;
        #pragma unroll
        for (int i = 0; i < 4; i++) {
            int e = tid + i * 256;
            cp16(dst + e * 16, g_B + 4 * 16384 + e * 16);
        }
        asm volatile("cp.async.commit_group;");
    }

    // --- phase 1: delta, exact fp32 rowsq, fp8 delta -> swizzled SMEM A ---
    {
        const int r0 = wid * 16;
        for (int rr = 0; rr < 16; rr++) {
            int r = r0 + rr;
            long gbase = (long)(m0 + r) * 128;
            float sq = 0.0f;
            uint32_t rswz = (uint32_t)(r & 7) << 4;
            #pragma unroll
            for (int q = 0; q < 4; q++) {
                int c4 = lane + q * 32;
                float4 xv = x4[gbase + c4];
                float4 fv = f4[gbase + c4];
                float d0 = xv.x - fv.x, d1 = xv.y - fv.y;
                float d2 = xv.z - fv.z, d3 = xv.w - fv.w;
                sq += d0 * d0 + d1 * d1 + d2 * d2 + d3 * d3;
                uint32_t v = (uint32_t)f2e4m3x2(d1, d0)
                           | ((uint32_t)f2e4m3x2(d3, d2) << 16);
                uint32_t off = (uint32_t)(r * 512)
                             + (((uint32_t)(c4 * 4)) ^ rswz);
                *(uint32_t*)(smem + SM_A + off) = v;
            }
            #pragma unroll
            for (int o = 16; o; o >>= 1)
                sq += __shfl_xor_sync(0xffffffffu, sq, o);
            if (lane == 0) rowsq[r] = sq;
        }
    }

    // --- phase 2: lower-triangle tiles, warp tile 64M x 32N,
    //     acc accumulated across kc inside each nc-group ---
    const int mb = wid >> 2;
    const int nb = wid & 3;
    const uint32_t aswz  = (uint32_t)(lane & 7) << 4;
    const uint32_t akoff = (uint32_t)(lane >> 4) << 4;
    const int bn1 = (lane & 7) + ((lane >> 4) << 3);
    const uint32_t bkoff = (uint32_t)((lane >> 3) & 1) << 4;

    uint32_t a_addr[4];
    #pragma unroll
    for (int sm = 0; sm < 4; sm++)
        a_addr[sm] = sbase + SM_A
                   + (uint32_t)((mb * 64 + sm * 16 + (lane & 15)) * 512);
    uint32_t b_off[2];
    #pragma unroll
    for (int sn = 0; sn < 2; sn++)
        b_off[sn] = (uint32_t)((nb * 32 + sn * 16 + bn1) * 128);

    // dot-side precomputed addressing
    const int rq = lane >> 2;
    uint32_t d_base[4];
    const uint32_t d_swz = (uint32_t)((mb * 64 + rq) & 7) << 4;
    #pragma unroll
    for (int sm = 0; sm < 4; sm++)
        d_base[sm] = (uint32_t)((mb * 64 + sm * 16 + rq) * 512);

    float acc[4][4][4];
    float zl[4] = {0, 0, 0, 0}, zh[4] = {0, 0, 0, 0};

    int p = 0;             // linear tile counter (buffer parity)
    int nc2 = 1, kc2 = 1;  // (nc,kc) of tile p+2

    for (int nc = 0; nc < 4; nc++) {
        // zero accumulators once per nc-group
        #pragma unroll
        for (int sm = 0; sm < 4; sm++)
            #pragma unroll
            for (int j = 0; j < 4; j++)
                #pragma unroll
                for (int q = 0; q < 4; q++)
                    acc[sm][j][q] = 0.0f;

        for (int kc = 0; kc <= nc; kc++) {
            asm volatile("cp.async.wait_group 1;" ::: "memory");
            __syncthreads();

            const uint32_t btile = sbase + SM_B + (p & 1) * 16384;

            #pragma unroll
            for (int s = 0; s < 4; s++) {
                uint32_t af[4][4], bf[2][4];
                uint32_t akb = (uint32_t)(kc * 128 + s * 32);
                #pragma unroll
                for (int sm = 0; sm < 4; sm++)
                    ldsm4(af[sm], a_addr[sm] + ((akb + akoff) ^ aswz));
                #pragma unroll
                for (int sn = 0; sn < 2; sn++)
                    ldsm4(bf[sn], btile + b_off[sn]
                          + (((uint32_t)(s * 32) + bkoff) ^ aswz));
                #pragma unroll
                for (int sm = 0; sm < 4; sm++)
                    #pragma unroll
                    for (int j = 0; j < 4; j++)
                        mma16832(acc[sm][j], af[sm], bf[j >> 1] + (j & 1) * 2);
            }

            __syncthreads();

            if (nc2 < 4) {
                uint32_t dst = sbase + SM_B + (p & 1) * 16384;
                const unsigned char* src = g_B + (nc2 * 4 + kc2) * 16384;
                #pragma unroll
                for (int i = 0; i < 4; i++) {
                    int e = tid + i * 256;
                    cp16(dst + e * 16, src + e * 16);
                }
            }
            asm volatile("cp.async.commit_group;");

            kc2++;
            if (kc2 > nc2) { nc2++; kc2 = 0; }
            p++;
        }

        // fused dot for this nc-group (weight already folded into B)
        #pragma unroll
        for (int sm = 0; sm < 4; sm++) {
            #pragma unroll
            for (int j = 0; j < 4; j++) {
                uint32_t kbyte = (uint32_t)(nc * 128 + nb * 32 + j * 8
                                            + (lane & 3) * 2);
                uint32_t off = kbyte ^ d_swz;
                uint16_t vlo = *(const uint16_t*)(smem + SM_A
                                   + d_base[sm] + off);
                uint16_t vhi = *(const uint16_t*)(smem + SM_A
                                   + d_base[sm] + 8 * 512 + off);
                float2 flo = e4m3x2_2f(vlo);
                float2 fhi = e4m3x2_2f(vhi);
                zl[sm] += flo.x * acc[sm][j][0] + flo.y * acc[sm][j][1];
                zh[sm] += fhi.x * acc[sm][j][2] + fhi.y * acc[sm][j][3];
            }
        }
    }

    // --- reduce over the 4 lanes of each quad-row group ---
    #pragma unroll
    for (int sm = 0; sm < 4; sm++) {
        zl[sm] += __shfl_xor_sync(0xffffffffu, zl[sm], 1);
        zl[sm] += __shfl_xor_sync(0xffffffffu, zl[sm], 2);
        zh[sm] += __shfl_xor_sync(0xffffffffu, zh[sm], 1);
        zh[sm] += __shfl_xor_sync(0xffffffffu, zh[sm], 2);
    }
    if ((lane & 3) == 0) {
        #pragma unroll
        for (int sm = 0; sm < 4; sm++) {
            int row = mb * 64 + sm * 16 + (lane >> 2);
            part[nb * 128 + row]     = zl[sm];
            part[nb * 128 + row + 8] = zh[sm];
        }
    }
    __syncthreads();
    if (tid < 128)
        out[m0 + tid] = rowsq[tid]
                      + (part[tid] + part[128 + tid]
                         + part[256 + tid] + part[384 + tid]) * (1.0f / 512.0f);
}

// ---------------------------------------------------------------------------
extern "C" void kernel_launch(void* const* d_in, const int* in_sizes, int n_in,
                              void* d_out, int out_size) {
    const float* x  = (const float*)d_in[0];
    const float* xf = (const float*)d_in[1];
    const float* S  = (const float*)d_in[2];
    float* out = (float*)d_out;

    cudaFuncSetAttribute(mahal_kernel,
                         cudaFuncAttributeMaxDynamicSharedMemorySize, SM_TOTAL);

    prep_kernel<<<512, 256>>>(S);
    mahal_kernel<<<NROWS / MTILE, 256, SM_TOTAL>>>(
        (const float4*)x, (const float4*)xf, out);
}